// round 17
// baseline (speedup 1.0000x reference)
#include <cuda_runtime.h>
#include <stdint.h>

#define N_POINTS 1200000
#define NFEAT 5
#define GXD 400
#define GYD 400
#define NCELLS (GXD*GYD)          // 160000
#define NCELLS_PAD 163840         // 40 * 4096
#define MAXV 60000
#define MAXP 32
#define OUT_COORD_OFF (MAXV*MAXP*NFEAT)        // 9,600,000
#define OUT_NUM_OFF   (OUT_COORD_OFF + MAXV*3) // 9,780,000
#define SCAN_BLOCKS 40
#define CELLS_PER_BLOCK 4096       // 1024 threads * 4 cells
#define DYN_TOTAL (NCELLS_PAD + SCAN_BLOCKS)
#define PPT 4

// [0,NCELLS_PAD) = per-cell list heads (0xFFFFFFFF = empty),
// then SCAN_BLOCKS lookback states. Re-initialized by memsets each launch.
__device__ unsigned g_dyn[DYN_TOTAL];
__device__ int      g_totvox;
__device__ uint2    g_voxlist[MAXV];           // {cell, head}
// rec[rpos(idx)] = {x,y,z,prev_bits}: ONE float4 per point, written truly
// coalesced (lanes at 16B stride). f3,f4 are gathered from pts in emit.
__device__ float4   g_rec[N_POINTS];

// bijection: idx = 128w + 4l' + k -> pos = 128w + 32k + l'  (lane-contiguous per k)
__device__ __forceinline__ unsigned rpos(unsigned idx) {
    return ((idx >> 7) << 7) | ((idx & 3u) << 5) | ((idx >> 2) & 31u);
}

__device__ __forceinline__ void do_point(int idx, unsigned pos,
                                         float x, float y, float z) {
    // exact: (v+50)*4 == (v-(-50))/0.25 ; (v+5)*0.125 == (v-(-5))/8
    int cx = (int)floorf((x + 50.0f) * 4.0f);
    int cy = (int)floorf((y + 50.0f) * 4.0f);
    int cz = (int)floorf((z + 5.0f) * 0.125f);
    if (cx >= 0 && cx < GXD && cy >= 0 && cy < GYD && cz == 0) {
        int cell = cy * GXD + cx;
        unsigned prev = atomicExch(&g_dyn[cell], (unsigned)idx);  // ONE scattered trans
        g_rec[pos] = make_float4(x, y, z, __uint_as_float(prev)); // coalesced across warp
    }
}

// ---------------- assign: linked-list push, 1 scattered transaction/point ----------------
__global__ void __launch_bounds__(256) k_assign(const float4* __restrict__ pts4) {
    int t = blockIdx.x * blockDim.x + threadIdx.x;
    if (t >= N_POINTS / PPT) return;
    const float4* src = pts4 + (size_t)t * 5;   // 5 aligned LDG.128, independent
    float4 q0 = src[0], q1 = src[1], q2 = src[2], q3 = src[3], q4 = src[4];
    int base = t * PPT;
    unsigned wb = (((unsigned)t >> 5) << 7) | ((unsigned)t & 31u);
    // point k = floats [5k,5k+5); rec pos = wb + 32k (lane-contiguous per k)
    do_point(base + 0, wb,      q0.x, q0.y, q0.z);
    do_point(base + 1, wb + 32, q1.y, q1.z, q1.w);
    do_point(base + 2, wb + 64, q2.z, q2.w, q3.x);
    do_point(base + 3, wb + 96, q3.w, q4.x, q4.y);
}

// ---------------- scan: single-wave decoupled lookback + voxel-list compaction ----------------
__global__ void __launch_bounds__(1024, 1) k_scan() {
    __shared__ int wsum[32];
    __shared__ unsigned s_prefix;
    unsigned* state = g_dyn + NCELLS_PAD;
    const int t = threadIdx.x, b = blockIdx.x;
    const int lane = t & 31, w = t >> 5;
    const int c0 = b * CELLS_PER_BLOCK + t * 4;

    uint4 c4 = *(const uint4*)&g_dyn[c0];
    int o0 = (c4.x != 0xFFFFFFFFu) ? 1 : 0;
    int o1 = (c4.y != 0xFFFFFFFFu) ? 1 : 0;
    int o2 = (c4.z != 0xFFFFFFFFu) ? 1 : 0;
    int o3 = (c4.w != 0xFFFFFFFFu) ? 1 : 0;
    int s = o0 + o1 + o2 + o3;

    int x = s;
    #pragma unroll
    for (int o = 1; o < 32; o <<= 1) {
        int v = __shfl_up_sync(0xffffffffu, x, o);
        if (lane >= o) x += v;
    }
    if (lane == 31) wsum[w] = x;
    __syncthreads();
    if (w == 0) {
        int y = wsum[lane];
        #pragma unroll
        for (int o = 1; o < 32; o <<= 1) {
            int v = __shfl_up_sync(0xffffffffu, y, o);
            if (lane >= o) y += v;
        }
        wsum[lane] = y;
    }
    __syncthreads();
    int incl = x + (w ? wsum[w - 1] : 0);
    unsigned agg = (unsigned)wsum[31];

    if (t == 0) {
        if (b == 0) atomicExch(&state[0], (2u << 30) | agg);
        else        atomicExch(&state[b], (1u << 30) | agg);
    }
    if (w == 0) {
        if (b == 0) { if (lane == 0) s_prefix = 0; }
        else {
            unsigned run = 0;
            int j = b - 1 - lane;
            for (;;) {
                unsigned sv = (j >= 0) ? *(volatile unsigned*)&state[j] : (2u << 30);
                unsigned flag = sv >> 30;
                if (__all_sync(0xffffffffu, flag != 0u)) {
                    unsigned pm = __ballot_sync(0xffffffffu, flag >= 2u);
                    int fp = (pm != 0u) ? (__ffs(pm) - 1) : -1;
                    unsigned contrib = (fp < 0 || lane <= fp) ? (sv & 0x3FFFFFFFu) : 0u;
                    #pragma unroll
                    for (int o = 16; o; o >>= 1)
                        contrib += __shfl_down_sync(0xffffffffu, contrib, o);
                    contrib = __shfl_sync(0xffffffffu, contrib, 0);
                    run += contrib;
                    if (fp >= 0) break;
                    j -= 32;
                }
            }
            if (lane == 0) {
                s_prefix = run;
                atomicExch(&state[b], (2u << 30) | (run + agg));
            }
        }
    }
    __syncthreads();

    int e = (int)s_prefix + incl - s;
    if (o0) { if (e < MAXV) g_voxlist[e] = make_uint2((unsigned)(c0+0), c4.x); e++; }
    if (o1) { if (e < MAXV) g_voxlist[e] = make_uint2((unsigned)(c0+1), c4.y); e++; }
    if (o2) { if (e < MAXV) g_voxlist[e] = make_uint2((unsigned)(c0+2), c4.z); e++; }
    if (o3) { if (e < MAXV) g_voxlist[e] = make_uint2((unsigned)(c0+3), c4.w); e++; }
    if (b == SCAN_BLOCKS - 1 && t == 1023) g_totvox = e;
}

// gather f3,f4 for point idx: floats 5i+3, 5i+4 (one 16B word unless (i+3)&3==3)
__device__ __forceinline__ void gather_tail(const float4* __restrict__ p4, int idx,
                                            float& f3, float& f4) {
    int w1 = (5 * idx + 3) >> 2;
    int o  = (idx + 3) & 3;
    float4 A = __ldg(&p4[w1]);
    f3 = o==0 ? A.x : o==1 ? A.y : o==2 ? A.z : A.w;
    if (o == 3) f4 = __ldg((const float*)&p4[w1 + 1]);
    else        f4 = o==0 ? A.y : o==1 ? A.z : A.w;
}

// ---------------- emit: half-warp per voxel; lane-0 list walk + parallel rec loads ----------------
__global__ void __launch_bounds__(256) k_emit(const float* __restrict__ pts,
                                              float* __restrict__ out) {
    int gid = blockIdx.x * blockDim.x + threadIdx.x;
    int gw  = gid >> 4;                   // voxel index (one per half-warp)
    int hl  = threadIdx.x & 15;           // lane within half
    int rg  = threadIdx.x >> 4;           // staging region 0..15 in block
    unsigned hmask = 0xFFFFu << (threadIdx.x & 16);
    __shared__ float sbuf[16][160];
    __shared__ int   sidx[16][32];

    if (gw >= MAXV) return;
    int tv = g_totvox;
    float4* dst = (float4*)(out + (size_t)gw * (MAXP * NFEAT));
    if (gw >= tv) {
        float4 z = make_float4(0.f, 0.f, 0.f, 0.f);
        for (int j = hl; j < 40; j += 16) __stcs(&dst[j], z);
        if (hl == 0) {
            float* oc = out + OUT_COORD_OFF + (size_t)gw * 3;
            __stcs(&oc[0], 0.f); __stcs(&oc[1], 0.f); __stcs(&oc[2], 0.f);
            __stcs(&out[OUT_NUM_OFF + gw], 0.f);
        }
        return;
    }

    uint2 ve = __ldcs(&g_voxlist[gw]);
    int cell = (int)ve.x;
    const float4* p4 = (const float4*)pts;

    // lane 0 of the half walks the list (avg ~4 hops), collecting point indices
    int m = 0;
    if (hl == 0) {
        unsigned h = ve.y;
        while (h != 0xFFFFFFFFu && m < 33) {
            if (m < 32) sidx[rg][m] = (int)h;
            m++;
            h = __float_as_uint(__ldg(((const float*)&g_rec[rpos(h)]) + 3));
        }
    }
    __syncwarp(hmask);
    m = __shfl_sync(hmask, m, 0, 16);

    float a0=0.f,a1=0.f,a2=0.f,a3=0.f,a4=0.f;   // record for slot hl
    float b0=0.f,b1=0.f,b2=0.f,b3=0.f,b4=0.f;   // record for slot hl+16
    int slotA, slotB, n;

    if (m <= MAXP) {
        n = m;
        int s0 = hl, s1 = hl + 16;
        int idxA = 0x7fffffff, idxB = 0x7fffffff;
        if (s0 < m) {
            idxA = sidx[rg][s0];
            float4 r = __ldg(&g_rec[rpos(idxA)]);
            a0 = r.x; a1 = r.y; a2 = r.z;
            gather_tail(p4, idxA, a3, a4);
        }
        if (s1 < m) {
            idxB = sidx[rg][s1];
            float4 r = __ldg(&g_rec[rpos(idxB)]);
            b0 = r.x; b1 = r.y; b2 = r.z;
            gather_tail(p4, idxB, b3, b4);
        }
        int rankA = 0, rankB = 0;
        int kA = m < 16 ? m : 16;
        for (int k = 0; k < kA; k++) {
            int o = __shfl_sync(hmask, idxA, k, 16);
            rankA += (o < idxA) ? 1 : 0;
            rankB += (o < idxB) ? 1 : 0;
        }
        if (m > 16) {
            int kB = m - 16;
            for (int k = 0; k < kB; k++) {
                int o = __shfl_sync(hmask, idxB, k, 16);
                rankA += (o < idxA) ? 1 : 0;
                rankB += (o < idxB) ? 1 : 0;
            }
        }
        slotA = (s0 < m) ? rankA : s0;   // active ranks tile [0,m), idles tile [m,32)
        slotB = (s1 < m) ? rankB : s1;
    } else {
        // overflow fallback (statistically never): first 32 matches scanning ascending j
        // are exactly the 32 smallest original indices, already in order.
        n = MAXP;
        slotA = hl; slotB = hl + 16;
        if (hl == 0) {
            int mm = 0;
            for (int j = 0; j < N_POINTS && mm < MAXP; j++) {
                const float* p = pts + (size_t)j * NFEAT;
                int cx = (int)floorf((p[0] + 50.0f) * 4.0f);
                int cy = (int)floorf((p[1] + 50.0f) * 4.0f);
                int cz = (int)floorf((p[2] + 5.0f) * 0.125f);
                if (cx >= 0 && cx < GXD && cy >= 0 && cy < GYD && cz == 0 &&
                    cy * GXD + cx == cell) sidx[rg][mm++] = j;
            }
        }
        __syncwarp(hmask);
        int iA = sidx[rg][hl], iB = sidx[rg][hl + 16];
        const float* pA = pts + (size_t)iA * NFEAT;
        const float* pB = pts + (size_t)iB * NFEAT;
        a0 = pA[0]; a1 = pA[1]; a2 = pA[2]; a3 = pA[3]; a4 = pA[4];
        b0 = pB[0]; b1 = pB[1]; b2 = pB[2]; b3 = pB[3]; b4 = pB[4];
    }

    // stage both records, then write the 640B voxel row coalesced (streaming)
    float* sb = sbuf[rg];
    float* dA = sb + slotA * NFEAT;
    dA[0] = a0; dA[1] = a1; dA[2] = a2; dA[3] = a3; dA[4] = a4;
    float* dB = sb + slotB * NFEAT;
    dB[0] = b0; dB[1] = b1; dB[2] = b2; dB[3] = b3; dB[4] = b4;
    __syncwarp(hmask);
    float4* s4 = (float4*)sb;
    #pragma unroll
    for (int j = hl; j < 40; j += 16) __stcs(&dst[j], s4[j]);
    if (hl == 0) {
        int cy = cell / GXD, cx = cell - cy * GXD;
        float* oc = out + OUT_COORD_OFF + (size_t)gw * 3;
        __stcs(&oc[0], 0.0f);           // z
        __stcs(&oc[1], (float)cy);      // y
        __stcs(&oc[2], (float)cx);      // x
        __stcs(&out[OUT_NUM_OFF + gw], (float)n);
    }
}

extern "C" void kernel_launch(void* const* d_in, const int* in_sizes, int n_in,
                              void* d_out, int out_size) {
    const float* pts = (const float*)d_in[0];
    float* out = (float*)d_out;
    (void)in_sizes; (void)n_in; (void)out_size;

    void* dynptr = nullptr;
    cudaGetSymbolAddress(&dynptr, g_dyn);
    // heads = 0xFFFFFFFF (empty lists), lookback state = 0
    cudaMemsetAsync(dynptr, 0xFF, sizeof(unsigned) * NCELLS_PAD, 0);
    cudaMemsetAsync((char*)dynptr + sizeof(unsigned) * NCELLS_PAD, 0,
                    sizeof(unsigned) * SCAN_BLOCKS, 0);

    k_assign<<<(N_POINTS / PPT + 255) / 256, 256>>>((const float4*)pts);
    k_scan  <<<SCAN_BLOCKS, 1024>>>();
    k_emit  <<<(MAXV * 16 + 255) / 256, 256>>>(pts, out);
}